// round 13
// baseline (speedup 1.0000x reference)
#include <cuda_runtime.h>
#include <cuda_bf16.h>
#include <float.h>
#include <math.h>
#include <stdint.h>

#define B_   2
#define NQ   2048
#define NKV  2048
#define C_   1024
#define H_   16
#define HD   64
#define M_   (B_*NQ)

typedef unsigned long long u64;
typedef unsigned int u32;
typedef __nv_bfloat16 bf;

// ---- mma.sync / ldmatrix helpers ----
__device__ __forceinline__ u32 smem_u32(const void* p) {
    u32 a;
    asm("{ .reg .u64 t; cvta.to.shared.u64 t, %1; cvt.u32.u64 %0, t; }" : "=r"(a) : "l"(p));
    return a;
}
__device__ __forceinline__ void mma_bf16(float* c, const u32* a, u32 b0, u32 b1) {
    asm volatile("mma.sync.aligned.m16n8k16.row.col.f32.bf16.bf16.f32 "
        "{%0,%1,%2,%3}, {%4,%5,%6,%7}, {%8,%9}, {%0,%1,%2,%3};"
        : "+f"(c[0]), "+f"(c[1]), "+f"(c[2]), "+f"(c[3])
        : "r"(a[0]), "r"(a[1]), "r"(a[2]), "r"(a[3]), "r"(b0), "r"(b1));
}
__device__ __forceinline__ void ldsm_x4(u32* r, u32 addr) {
    asm volatile("ldmatrix.sync.aligned.m8n8.x4.shared.b16 {%0,%1,%2,%3}, [%4];"
        : "=r"(r[0]), "=r"(r[1]), "=r"(r[2]), "=r"(r[3]) : "r"(addr));
}
__device__ __forceinline__ void ldsm_x4t(u32* r, u32 addr) {
    asm volatile("ldmatrix.sync.aligned.m8n8.x4.trans.shared.b16 {%0,%1,%2,%3}, [%4];"
        : "=r"(r[0]), "=r"(r[1]), "=r"(r[2]), "=r"(r[3]) : "r"(addr));
}
__device__ __forceinline__ void cpa16(u32 dst, const void* src) {
    asm volatile("cp.async.cg.shared.global [%0], [%1], 16;" :: "r"(dst), "l"(src));
}
#define CPA_COMMIT() asm volatile("cp.async.commit_group;" ::: "memory")
#define CPA_WAIT2()  asm volatile("cp.async.wait_group 2;" ::: "memory")
#define CPA_WAIT1()  asm volatile("cp.async.wait_group 1;" ::: "memory")

__device__ __forceinline__ float ex2(float x) {
    float r; asm("ex2.approx.f32 %0, %1;" : "=f"(r) : "f"(x)); return r;
}
__device__ __forceinline__ void bsplit(float x, bf& h, bf& l) {
    h = __float2bfloat16(x);
    l = __float2bfloat16(x - __bfloat162float(h));
}
__device__ __forceinline__ u32 pack_bf(bf a, bf b) {
    return (u32)__bfloat16_as_ushort(a) | ((u32)__bfloat16_as_ushort(b) << 16);
}
__device__ __forceinline__ u32 split_pack_hi(float a, float b, u32& lo) {
    bf ha, la, hb, lb;
    bsplit(a, ha, la); bsplit(b, hb, lb);
    lo = pack_bf(la, lb);
    return pack_bf(ha, hb);
}

// ---- scratch ----
__device__ bf g_Iqh[M_*C_], g_Iql[M_*C_];
__device__ bf g_Ikh[M_*C_], g_Ikl[M_*C_];
__device__ bf g_Ivh[M_*C_], g_Ivl[M_*C_];
__device__ bf g_Wqh[C_*C_], g_Wql[C_*C_];
__device__ bf g_Wkh[C_*C_], g_Wkl[C_*C_];
__device__ bf g_Wvh[C_*C_], g_Wvl[C_*C_];
__device__ bf g_Wph[C_*C_], g_Wpl[C_*C_];
__device__ bf g_Qh[B_*H_*NQ*HD],  g_Ql[B_*H_*NQ*HD];
__device__ bf g_Kh[B_*H_*NKV*HD], g_Kl[B_*H_*NKV*HD];
__device__ bf g_Vh[B_*H_*NKV*HD], g_Vl[B_*H_*NKV*HD];
__device__ bf g_Xh[M_*C_], g_Xl[M_*C_];
__device__ float g_cosT[NKV*HD], g_sinT[NKV*HD];

// ============================================================================
// Merged prep: splits of inputs/weights + cos/sin table in ONE launch.
// grid (4096, 1, 8); z=0..2 inputs, z=3..6 weights (guarded), z=7 cossin.
// ============================================================================
__device__ __forceinline__ void split_one(const float* v, bf* oh, bf* ol, int i) {
    float4 x = ((const float4*)v)[i];
    u32 l0, l1;
    u32 h0 = split_pack_hi(x.x, x.y, l0);
    u32 h1 = split_pack_hi(x.z, x.w, l1);
    ((u32*)oh)[2*i] = h0; ((u32*)oh)[2*i+1] = h1;
    ((u32*)ol)[2*i] = l0; ((u32*)ol)[2*i+1] = l1;
}
__global__ __launch_bounds__(256)
void prep_all(const float* q, const float* k, const float* v,
              const float* wq, const float* wk, const float* wv, const float* wp,
              const float* pos)
{
    int i = blockIdx.x * 256 + threadIdx.x;
    int z = blockIdx.z;
    if (z == 0)      split_one(q, g_Iqh, g_Iql, i);
    else if (z == 1) split_one(k, g_Ikh, g_Ikl, i);
    else if (z == 2) split_one(v, g_Ivh, g_Ivl, i);
    else if (z == 7) {
        if (i < NKV * HD) {
            float s, c;
            sincosf(pos[i], &s, &c);
            g_cosT[i] = c; g_sinT[i] = s;
        }
    } else {
        if (i < C_ * C_ / 4) {
            if (z == 3)      split_one(wq, g_Wqh, g_Wql, i);
            else if (z == 4) split_one(wk, g_Wkh, g_Wkl, i);
            else if (z == 5) split_one(wv, g_Wvh, g_Wvl, i);
            else             split_one(wp, g_Wph, g_Wpl, i);
        }
    }
}

// ============================================================================
// Split-bf16 tensor-core GEMM — 3-stage cp.async ring, ONE sync per kc-iter.
// CTA 128x128, 8 warps (4m x 2n), K-chunk 32. Tight pads: A row 40 elems
// (bank pattern r*20%32 — conflict-free), W row 136 elems (r*68%32 — c-free).
// Stage = 37888 B, 3 stages = 113664 B < 114 KB -> 2 CTAs/SM kept.
// ============================================================================
#define GA_PAD 40
#define GW_PAD 136
#define GS_AH 0
#define GS_AL (128*GA_PAD*2)                 // 10240
#define GS_WH (2*128*GA_PAD*2)               // 20480
#define GS_WL (GS_WH + 32*GW_PAD*2)          // 29184
#define GS_STAGE (GS_WL + 32*GW_PAD*2)       // 37888
#define GS_TOTAL (3*GS_STAGE)                // 113664

template<int EPI>
__device__ __forceinline__
void gemm_tc_body(const bf* __restrict__ Ah, const bf* __restrict__ Al,
                  const bf* __restrict__ Wh, const bf* __restrict__ Wl,
                  float* __restrict__ outF, bf* __restrict__ Oh, bf* __restrict__ Ol,
                  float scale)
{
    extern __shared__ char gsm[];
    const u32 dynu = smem_u32(gsm);
    const int tid = threadIdx.x;
    const int wid = tid >> 5, lane = tid & 31;
    const int wm = wid >> 1, wn = wid & 1;
    const int m0 = blockIdx.y * 128, n0 = blockIdx.x * 128;

    auto load_stage = [&](int s, int kc) {
        u32 sb = dynu + s * GS_STAGE;
        #pragma unroll
        for (int i = tid; i < 512; i += 256) {
            int r = i >> 2, c = i & 3;
            u32 off = (u32)(r * GA_PAD + c * 8) * 2;
            cpa16(sb + GS_AH + off, Ah + (size_t)(m0 + r) * C_ + kc * 32 + c * 8);
            cpa16(sb + GS_AL + off, Al + (size_t)(m0 + r) * C_ + kc * 32 + c * 8);
        }
        #pragma unroll
        for (int i = tid; i < 512; i += 256) {
            int r = i >> 4, c = i & 15;
            u32 off = (u32)(r * GW_PAD + c * 8) * 2;
            cpa16(sb + GS_WH + off, Wh + (size_t)(kc * 32 + r) * C_ + n0 + c * 8);
            cpa16(sb + GS_WL + off, Wl + (size_t)(kc * 32 + r) * C_ + n0 + c * 8);
        }
    };

    float acc[2][8][4];
    #pragma unroll
    for (int mt = 0; mt < 2; mt++)
        #pragma unroll
        for (int nn = 0; nn < 8; nn++)
            #pragma unroll
            for (int p = 0; p < 4; p++) acc[mt][nn][p] = 0.f;

    load_stage(0, 0); CPA_COMMIT();
    load_stage(1, 1); CPA_COMMIT();

    const u32 aLane  = (u32)((lane & 15) * GA_PAD + ((lane >> 4) << 3)) * 2;
    const u32 wLane4 = (u32)((lane & 15) * GW_PAD + ((lane >> 4) & 1) * 8) * 2;

    for (int kc = 0; kc < 32; kc++) {
        const int s = kc % 3;
        CPA_WAIT1();            // tile kc complete (pending: kc, kc+1)
        __syncthreads();        // publish tile kc; certifies stage (kc-1)%3 free
        if (kc + 2 < 32) load_stage((kc + 2) % 3, kc + 2);
        CPA_COMMIT();           // committed every iter to keep group count fixed

        u32 sb = dynu + s * GS_STAGE;
        u32 ah[2][2][4], al[2][2][4];
        #pragma unroll
        for (int mt = 0; mt < 2; mt++)
            #pragma unroll
            for (int kk = 0; kk < 2; kk++) {
                u32 off = (u32)((wm * 32 + mt * 16) * GA_PAD + kk * 16) * 2 + aLane;
                ldsm_x4(ah[mt][kk], sb + GS_AH + off);
                ldsm_x4(al[mt][kk], sb + GS_AL + off);
            }
        #pragma unroll
        for (int kk = 0; kk < 2; kk++)
            #pragma unroll
            for (int nn = 0; nn < 8; nn += 2) {
                u32 off = (u32)(kk * 16 * GW_PAD + wn * 64 + nn * 8) * 2 + wLane4;
                u32 bh4[4], bl4[4];
                ldsm_x4t(bh4, sb + GS_WH + off);
                ldsm_x4t(bl4, sb + GS_WL + off);
                #pragma unroll
                for (int mt = 0; mt < 2; mt++) {
                    mma_bf16(acc[mt][nn],     ah[mt][kk], bh4[0], bh4[1]);
                    mma_bf16(acc[mt][nn],     ah[mt][kk], bl4[0], bl4[1]);
                    mma_bf16(acc[mt][nn],     al[mt][kk], bh4[0], bh4[1]);
                    mma_bf16(acc[mt][nn + 1], ah[mt][kk], bh4[2], bh4[3]);
                    mma_bf16(acc[mt][nn + 1], ah[mt][kk], bl4[2], bl4[3]);
                    mma_bf16(acc[mt][nn + 1], al[mt][kk], bh4[2], bh4[3]);
                }
            }
    }

    // ---- epilogue ----
    const int g = lane >> 2, tig = lane & 3;
    if (EPI == 0) {
        #pragma unroll
        for (int mt = 0; mt < 2; mt++) {
            int row = m0 + wm * 32 + mt * 16 + g;
            #pragma unroll
            for (int nn = 0; nn < 8; nn++) {
                int n = n0 + nn * 8 + wn * 64 + 2 * tig;
                *(float2*)(outF + (size_t)row * C_ + n) =
                    make_float2(acc[mt][nn][0], acc[mt][nn][1]);
                *(float2*)(outF + (size_t)(row + 8) * C_ + n) =
                    make_float2(acc[mt][nn][2], acc[mt][nn][3]);
            }
        }
    } else {
        const int hh = (n0 + wn * 64) >> 6;
        #pragma unroll
        for (int mt = 0; mt < 2; mt++) {
            #pragma unroll
            for (int rr = 0; rr < 2; rr++) {
                int row = m0 + wm * 32 + mt * 16 + g + rr * 8;
                int b = row >> 11, l = row & 2047;
                size_t base = ((size_t)(b * H_ + hh) * NQ + l) * 64;
                int ci = rr * 2;
                if (EPI == 1) {
                    #pragma unroll
                    for (int nn = 0; nn < 4; nn++) {
                        int d0 = nn * 8 + 2 * tig;
                        float x1a = acc[mt][nn][ci],     x1b = acc[mt][nn][ci + 1];
                        float x2a = acc[mt][nn + 4][ci], x2b = acc[mt][nn + 4][ci + 1];
                        float2 c1 = *(const float2*)(g_cosT + l * 64 + d0);
                        float2 s1 = *(const float2*)(g_sinT + l * 64 + d0);
                        float2 c2 = *(const float2*)(g_cosT + l * 64 + d0 + 32);
                        float2 s2 = *(const float2*)(g_sinT + l * 64 + d0 + 32);
                        float y1a = scale * (x1a * c1.x - x2a * s1.x);
                        float y1b = scale * (x1b * c1.y - x2b * s1.y);
                        float y2a = scale * (x2a * c2.x + x1a * s2.x);
                        float y2b = scale * (x2b * c2.y + x1b * s2.y);
                        u32 lo1, lo2;
                        u32 hi1 = split_pack_hi(y1a, y1b, lo1);
                        u32 hi2 = split_pack_hi(y2a, y2b, lo2);
                        *(u32*)(Oh + base + d0)      = hi1;
                        *(u32*)(Ol + base + d0)      = lo1;
                        *(u32*)(Oh + base + d0 + 32) = hi2;
                        *(u32*)(Ol + base + d0 + 32) = lo2;
                    }
                } else {
                    #pragma unroll
                    for (int nn = 0; nn < 8; nn++) {
                        int d0 = nn * 8 + 2 * tig;
                        u32 lo;
                        u32 hi = split_pack_hi(acc[mt][nn][ci], acc[mt][nn][ci + 1], lo);
                        *(u32*)(Oh + base + d0) = hi;
                        *(u32*)(Ol + base + d0) = lo;
                    }
                }
            }
        }
    }
}

// Q scale folds log2(e) so attention can use raw ex2.
#define QSCALE (0.125f * 1.4426950408889634f)

__global__ __launch_bounds__(256)
void gemm3_bf16()
{
    int z = blockIdx.z;
    if (z == 0)
        gemm_tc_body<1>(g_Iqh, g_Iql, g_Wqh, g_Wql, nullptr, g_Qh, g_Ql, QSCALE);
    else if (z == 1)
        gemm_tc_body<1>(g_Ikh, g_Ikl, g_Wkh, g_Wkl, nullptr, g_Kh, g_Kl, 1.0f);
    else
        gemm_tc_body<2>(g_Ivh, g_Ivl, g_Wvh, g_Wvl, nullptr, g_Vh, g_Vl, 1.0f);
}
__global__ __launch_bounds__(256)
void gemm1_bf16(float* __restrict__ out)
{
    gemm_tc_body<0>(g_Xh, g_Xl, g_Wph, g_Wpl, out, nullptr, nullptr, 1.0f);
}

// ============================================================================
// Flash attention (R12 config, measured ~262us): 64-row/128-thread CTA,
// K double-buffered cp.async, V single-buffered, 4 CTAs/SM, ex2 softmax.
// ============================================================================
#define ROWP 72
#define ATILE (64*ROWP*2)
#define KSTAGE (2*ATILE)
#define ATT_SMEM (2*KSTAGE + KSTAGE)

__global__ __launch_bounds__(128, 4)
void attn_mma(const int* __restrict__ mask)
{
    extern __shared__ char asm_raw[];
    __shared__ int s_mask[2][64];

    const int tid  = threadIdx.x;
    const int wid  = tid >> 5, lane = tid & 31;
    const int g    = lane >> 2, tig = lane & 3;
    const int bh   = blockIdx.x, b = bh >> 4, h = bh & 15;
    const int q0   = blockIdx.y * 64;
    const int r0   = wid * 16;

    const u32 base0 = smem_u32(asm_raw);
    const u32 vbase = base0 + 2 * KSTAGE;

    const bf* Khg = g_Kh + (size_t)bh * NKV * HD;
    const bf* Klg = g_Kl + (size_t)bh * NKV * HD;
    const bf* Vhg = g_Vh + (size_t)bh * NKV * HD;
    const bf* Vlg = g_Vl + (size_t)bh * NKV * HD;

    auto load_K = [&](int s, int t) {
        u32 sb = base0 + s * KSTAGE;
        const bf* kh = Khg + (size_t)t * 64 * HD;
        const bf* kl = Klg + (size_t)t * 64 * HD;
        #pragma unroll
        for (int i = tid; i < 512; i += 128) {
            int row = i >> 3, c8 = i & 7;
            u32 off = (u32)(row * ROWP + c8 * 8) * 2;
            const int gsrc = row * 64 + c8 * 8;
            cpa16(sb + off,         kh + gsrc);
            cpa16(sb + ATILE + off, kl + gsrc);
        }
    };
    auto load_V = [&](int t) {
        const bf* vh = Vhg + (size_t)t * 64 * HD;
        const bf* vl = Vlg + (size_t)t * 64 * HD;
        #pragma unroll
        for (int i = tid; i < 512; i += 128) {
            int row = i >> 3, c8 = i & 7;
            u32 off = (u32)(row * ROWP + c8 * 8) * 2;
            const int gsrc = row * 64 + c8 * 8;
            cpa16(vbase + off,         vh + gsrc);
            cpa16(vbase + ATILE + off, vl + gsrc);
        }
        if (tid < 64) s_mask[t & 1][tid] = mask[b * NKV + t * 64 + tid];
    };

    load_K(0, 0); CPA_COMMIT();
    {
        const bf* qh = g_Qh + ((size_t)bh * NQ + q0) * HD;
        const bf* ql = g_Ql + ((size_t)bh * NQ + q0) * HD;
        bf* dKh = (bf*)(asm_raw + KSTAGE);
        bf* dKl = (bf*)(asm_raw + KSTAGE + ATILE);
        for (int i = tid; i < 512; i += 128) {
            int row = i >> 3, c8 = i & 7;
            *(float4*)(dKh + row * ROWP + c8 * 8) = *(const float4*)(qh + row * 64 + c8 * 8);
            *(float4*)(dKl + row * ROWP + c8 * 8) = *(const float4*)(ql + row * 64 + c8 * 8);
        }
    }
    __syncthreads();

    u32 qh[4][4], ql[4][4];
    {
        u32 rowoff = (u32)((r0 + (lane & 15)) * ROWP + ((lane >> 4) << 3)) * 2;
        #pragma unroll
        for (int kk = 0; kk < 4; kk++) {
            ldsm_x4(qh[kk], base0 + KSTAGE + rowoff + kk * 32);
            ldsm_x4(ql[kk], base0 + KSTAGE + ATILE + rowoff + kk * 32);
        }
    }

    float oacc[8][4];
    #pragma unroll
    for (int nn = 0; nn < 8; nn++)
        #pragma unroll
        for (int p = 0; p < 4; p++) oacc[nn][p] = 0.f;
    float lacc0 = 0.f, lacc1 = 0.f;

    const u32 kAddr4 = (u32)((lane & 7) * ROWP + ((lane >> 3) & 1) * 8
                             + ((lane >> 4) & 1) * 8 * ROWP) * 2;
    const u32 vAddr4 = (u32)((lane & 15) * ROWP + ((lane >> 4) & 1) * 8) * 2;

    for (int t = 0; t < NKV / 64; t++) {
        const int s = t & 1;
        __syncthreads();
        load_V(t); CPA_COMMIT();
        if (t + 1 < NKV / 64) load_K(s ^ 1, t + 1);
        CPA_COMMIT();
        CPA_WAIT2();
        __syncthreads();

        const u32 sbK = base0 + s * KSTAGE;

        float sacc[8][4];
        #pragma unroll
        for (int nn = 0; nn < 8; nn++)
            #pragma unroll
            for (int p = 0; p < 4; p++) sacc[nn][p] = 0.f;

        #pragma unroll
        for (int kk = 0; kk < 4; kk++) {
            #pragma unroll
            for (int nn = 0; nn < 8; nn += 2) {
                u32 off = kAddr4 + (u32)(nn * 8 * ROWP + kk * 16) * 2;
                u32 bh4[4], bl4[4];
                ldsm_x4(bh4, sbK + off);
                ldsm_x4(bl4, sbK + ATILE + off);
                mma_bf16(sacc[nn],     qh[kk], bh4[0], bh4[1]);
                mma_bf16(sacc[nn],     qh[kk], bl4[0], bl4[1]);
                mma_bf16(sacc[nn],     ql[kk], bh4[0], bh4[1]);
                mma_bf16(sacc[nn + 1], qh[kk], bh4[2], bh4[3]);
                mma_bf16(sacc[nn + 1], qh[kk], bl4[2], bl4[3]);
                mma_bf16(sacc[nn + 1], ql[kk], bh4[2], bh4[3]);
            }
        }

        u32 ph[4][4], pl[4][4];
        #pragma unroll
        for (int nn = 0; nn < 8; nn++) {
            int m0 = s_mask[s][nn*8 + 2*tig], m1 = s_mask[s][nn*8 + 2*tig + 1];
            float p00 = m0 ? ex2(sacc[nn][0]) : 0.f;
            float p01 = m1 ? ex2(sacc[nn][1]) : 0.f;
            float p10 = m0 ? ex2(sacc[nn][2]) : 0.f;
            float p11 = m1 ? ex2(sacc[nn][3]) : 0.f;
            lacc0 += p00 + p01;
            lacc1 += p10 + p11;
            int kk = nn >> 1, hi = nn & 1;
            u32 lo;
            ph[kk][hi ? 2 : 0] = split_pack_hi(p00, p01, lo); pl[kk][hi ? 2 : 0] = lo;
            ph[kk][hi ? 3 : 1] = split_pack_hi(p10, p11, lo); pl[kk][hi ? 3 : 1] = lo;
        }

        CPA_WAIT1();
        __syncthreads();

        #pragma unroll
        for (int kk = 0; kk < 4; kk++) {
            #pragma unroll
            for (int nn = 0; nn < 8; nn += 2) {
                u32 off = vAddr4 + (u32)(kk * 16 * ROWP + nn * 8) * 2;
                u32 bh4[4], bl4[4];
                ldsm_x4t(bh4, vbase + off);
                ldsm_x4t(bl4, vbase + ATILE + off);
                mma_bf16(oacc[nn],     ph[kk], bh4[0], bh4[1]);
                mma_bf16(oacc[nn],     ph[kk], bl4[0], bl4[1]);
                mma_bf16(oacc[nn],     pl[kk], bh4[0], bh4[1]);
                mma_bf16(oacc[nn + 1], ph[kk], bh4[2], bh4[3]);
                mma_bf16(oacc[nn + 1], ph[kk], bl4[2], bl4[3]);
                mma_bf16(oacc[nn + 1], pl[kk], bh4[2], bh4[3]);
            }
        }
    }

    lacc0 += __shfl_xor_sync(0xffffffffu, lacc0, 1);
    lacc0 += __shfl_xor_sync(0xffffffffu, lacc0, 2);
    lacc1 += __shfl_xor_sync(0xffffffffu, lacc1, 1);
    lacc1 += __shfl_xor_sync(0xffffffffu, lacc1, 2);
    float inv0 = 1.f / lacc0, inv1 = 1.f / lacc1;

    int row0 = q0 + r0 + g, row1 = row0 + 8;
    size_t base0x = (size_t)(b * NQ + row0) * C_ + h * 64;
    size_t base1x = (size_t)(b * NQ + row1) * C_ + h * 64;
    #pragma unroll
    for (int nn = 0; nn < 8; nn++) {
        int c = nn * 8 + 2 * tig;
        u32 lo;
        u32 hi = split_pack_hi(oacc[nn][0] * inv0, oacc[nn][1] * inv0, lo);
        *(u32*)(g_Xh + base0x + c) = hi;
        *(u32*)(g_Xl + base0x + c) = lo;
        hi = split_pack_hi(oacc[nn][2] * inv1, oacc[nn][3] * inv1, lo);
        *(u32*)(g_Xh + base1x + c) = hi;
        *(u32*)(g_Xl + base1x + c) = lo;
    }
}

// ============================================================================
extern "C" void kernel_launch(void* const* d_in, const int* in_sizes, int n_in,
                              void* d_out, int out_size)
{
    const float* q    = (const float*)d_in[0];
    const float* k    = (const float*)d_in[1];
    const float* v    = (const float*)d_in[2];
    const int*   mask = (const int*)  d_in[3];
    const float* pos  = (const float*)d_in[4];
    const float* qW   = (const float*)d_in[5];
    const float* kW   = (const float*)d_in[6];
    const float* vW   = (const float*)d_in[7];
    const float* pW   = (const float*)d_in[8];
    float* out = (float*)d_out;

    cudaFuncSetAttribute(gemm3_bf16, cudaFuncAttributeMaxDynamicSharedMemorySize, GS_TOTAL);
    cudaFuncSetAttribute(gemm1_bf16, cudaFuncAttributeMaxDynamicSharedMemorySize, GS_TOTAL);
    cudaFuncSetAttribute(attn_mma,  cudaFuncAttributeMaxDynamicSharedMemorySize, ATT_SMEM);

    // merged conversions (one launch)
    prep_all<<<dim3((M_*C_/4)/256, 1, 8), 256>>>(q, k, v, qW, kW, vW, pW, pos);

    // projections + fused RoPE/split epilogues (tensor core)
    gemm3_bf16<<<dim3(C_/128, M_/128, 3), 256, GS_TOTAL>>>();

    // attention (tensor core)
    attn_mma<<<dim3(B_ * H_, NQ / 64), 128, ATT_SMEM>>>(mask);

    // output projection (tensor core)
    gemm1_bf16<<<dim3(C_/128, M_/128, 1), 256, GS_TOTAL>>>(out);
}

// round 14
// speedup vs baseline: 1.0592x; 1.0592x over previous
#include <cuda_runtime.h>
#include <cuda_bf16.h>
#include <float.h>
#include <math.h>
#include <stdint.h>

#define B_   2
#define NQ   2048
#define NKV  2048
#define C_   1024
#define H_   16
#define HD   64
#define M_   (B_*NQ)

typedef unsigned long long u64;
typedef unsigned int u32;
typedef __nv_bfloat16 bf;

// ---- mma.sync / ldmatrix helpers ----
__device__ __forceinline__ u32 smem_u32(const void* p) {
    u32 a;
    asm("{ .reg .u64 t; cvta.to.shared.u64 t, %1; cvt.u32.u64 %0, t; }" : "=r"(a) : "l"(p));
    return a;
}
__device__ __forceinline__ void mma_bf16(float* c, const u32* a, u32 b0, u32 b1) {
    asm volatile("mma.sync.aligned.m16n8k16.row.col.f32.bf16.bf16.f32 "
        "{%0,%1,%2,%3}, {%4,%5,%6,%7}, {%8,%9}, {%0,%1,%2,%3};"
        : "+f"(c[0]), "+f"(c[1]), "+f"(c[2]), "+f"(c[3])
        : "r"(a[0]), "r"(a[1]), "r"(a[2]), "r"(a[3]), "r"(b0), "r"(b1));
}
__device__ __forceinline__ void ldsm_x4(u32* r, u32 addr) {
    asm volatile("ldmatrix.sync.aligned.m8n8.x4.shared.b16 {%0,%1,%2,%3}, [%4];"
        : "=r"(r[0]), "=r"(r[1]), "=r"(r[2]), "=r"(r[3]) : "r"(addr));
}
__device__ __forceinline__ void ldsm_x4t(u32* r, u32 addr) {
    asm volatile("ldmatrix.sync.aligned.m8n8.x4.trans.shared.b16 {%0,%1,%2,%3}, [%4];"
        : "=r"(r[0]), "=r"(r[1]), "=r"(r[2]), "=r"(r[3]) : "r"(addr));
}
__device__ __forceinline__ void cpa16(u32 dst, const void* src) {
    asm volatile("cp.async.cg.shared.global [%0], [%1], 16;" :: "r"(dst), "l"(src));
}
#define CPA_COMMIT() asm volatile("cp.async.commit_group;" ::: "memory")
#define CPA_WAIT2()  asm volatile("cp.async.wait_group 2;" ::: "memory")
#define CPA_WAIT1()  asm volatile("cp.async.wait_group 1;" ::: "memory")

__device__ __forceinline__ float ex2(float x) {
    float r; asm("ex2.approx.f32 %0, %1;" : "=f"(r) : "f"(x)); return r;
}
// Packed hi/lo split: hi = {bf16(b),bf16(a)}, lo = {bf16(b-hb),bf16(a-ha)}.
// Bit-identical to scalar __float2bfloat16 path (same rn rounding).
__device__ __forceinline__ u32 split_pack_hi(float a, float b, u32& lo) {
    u32 hi;
    asm("cvt.rn.bf16x2.f32 %0, %1, %2;" : "=r"(hi) : "f"(b), "f"(a));
    float fa = __uint_as_float(hi << 16);
    float fb = __uint_as_float(hi & 0xFFFF0000u);
    float la = a - fa, lb = b - fb;
    asm("cvt.rn.bf16x2.f32 %0, %1, %2;" : "=r"(lo) : "f"(lb), "f"(la));
    return hi;
}

// ---- scratch ----
__device__ bf g_Iqh[M_*C_], g_Iql[M_*C_];
__device__ bf g_Ikh[M_*C_], g_Ikl[M_*C_];
__device__ bf g_Ivh[M_*C_], g_Ivl[M_*C_];
__device__ bf g_Wqh[C_*C_], g_Wql[C_*C_];
__device__ bf g_Wkh[C_*C_], g_Wkl[C_*C_];
__device__ bf g_Wvh[C_*C_], g_Wvl[C_*C_];
__device__ bf g_Wph[C_*C_], g_Wpl[C_*C_];
__device__ bf g_Qh[B_*H_*NQ*HD],  g_Ql[B_*H_*NQ*HD];
__device__ bf g_Kh[B_*H_*NKV*HD], g_Kl[B_*H_*NKV*HD];
__device__ bf g_Vh[B_*H_*NKV*HD], g_Vl[B_*H_*NKV*HD];
__device__ bf g_Xh[M_*C_], g_Xl[M_*C_];
__device__ float g_cosT[NKV*HD], g_sinT[NKV*HD];

// ============================================================================
// Merged prep in ONE launch, 1-D packed grid (no idle blocks):
// [0,4096) q | [4096,8192) k | [8192,12288) v | [12288,13312) wq |
// [13312,14336) wk | [14336,15360) wv | [15360,16384) wp | [16384,16896) cossin
// ============================================================================
#define PREP_BLOCKS 16896

__device__ __forceinline__ void split_one(const float* v, bf* oh, bf* ol, int i) {
    float4 x = ((const float4*)v)[i];
    u32 l0, l1;
    u32 h0 = split_pack_hi(x.x, x.y, l0);
    u32 h1 = split_pack_hi(x.z, x.w, l1);
    ((u32*)oh)[2*i] = h0; ((u32*)oh)[2*i+1] = h1;
    ((u32*)ol)[2*i] = l0; ((u32*)ol)[2*i+1] = l1;
}
__global__ __launch_bounds__(256)
void prep_all(const float* q, const float* k, const float* v,
              const float* wq, const float* wk, const float* wv, const float* wp,
              const float* pos)
{
    int bx = blockIdx.x;
    int tid = threadIdx.x;
    if (bx < 12288) {
        int z = bx >> 12;              // /4096
        int i = (bx & 4095) * 256 + tid;
        if (z == 0)      split_one(q, g_Iqh, g_Iql, i);
        else if (z == 1) split_one(k, g_Ikh, g_Ikl, i);
        else             split_one(v, g_Ivh, g_Ivl, i);
    } else if (bx < 16384) {
        int r = bx - 12288;
        int z = r >> 10;               // /1024
        int i = (r & 1023) * 256 + tid;
        if (z == 0)      split_one(wq, g_Wqh, g_Wql, i);
        else if (z == 1) split_one(wk, g_Wkh, g_Wkl, i);
        else if (z == 2) split_one(wv, g_Wvh, g_Wvl, i);
        else             split_one(wp, g_Wph, g_Wpl, i);
    } else {
        int i = (bx - 16384) * 256 + tid;   // < NKV*HD = 131072
        float s, c;
        sincosf(pos[i], &s, &c);
        g_cosT[i] = c; g_sinT[i] = s;
    }
}

// ============================================================================
// Split-bf16 tensor-core GEMM (exact R12 config, measured 238us for 3 GEMMs):
// CTA 128x128, 8 warps (4m x 2n), K-chunk 32, 2-stage cp.async, x4t B-loads,
// pads 56/152, 96 KB smem -> 2 CTAs/SM.
// ============================================================================
#define GS_AH 0
#define GS_AL 14336
#define GS_WH 28672
#define GS_WL 38400
#define GS_STAGE 48128
#define GS_TOTAL (2*GS_STAGE)

template<int EPI>
__device__ __forceinline__
void gemm_tc_body(const bf* __restrict__ Ah, const bf* __restrict__ Al,
                  const bf* __restrict__ Wh, const bf* __restrict__ Wl,
                  float* __restrict__ outF, bf* __restrict__ Oh, bf* __restrict__ Ol,
                  float scale)
{
    extern __shared__ char gsm[];
    const u32 dynu = smem_u32(gsm);
    const int tid = threadIdx.x;
    const int wid = tid >> 5, lane = tid & 31;
    const int wm = wid >> 1, wn = wid & 1;
    const int m0 = blockIdx.y * 128, n0 = blockIdx.x * 128;

    auto load_stage = [&](int s, int kc) {
        u32 sb = dynu + s * GS_STAGE;
        #pragma unroll
        for (int i = tid; i < 512; i += 256) {
            int r = i >> 2, c = i & 3;
            u32 off = (u32)(r * 56 + c * 8) * 2;
            cpa16(sb + GS_AH + off, Ah + (size_t)(m0 + r) * C_ + kc * 32 + c * 8);
            cpa16(sb + GS_AL + off, Al + (size_t)(m0 + r) * C_ + kc * 32 + c * 8);
        }
        #pragma unroll
        for (int i = tid; i < 512; i += 256) {
            int r = i >> 4, c = i & 15;
            u32 off = (u32)(r * 152 + c * 8) * 2;
            cpa16(sb + GS_WH + off, Wh + (size_t)(kc * 32 + r) * C_ + n0 + c * 8);
            cpa16(sb + GS_WL + off, Wl + (size_t)(kc * 32 + r) * C_ + n0 + c * 8);
        }
    };

    float acc[2][8][4];
    #pragma unroll
    for (int mt = 0; mt < 2; mt++)
        #pragma unroll
        for (int nn = 0; nn < 8; nn++)
            #pragma unroll
            for (int p = 0; p < 4; p++) acc[mt][nn][p] = 0.f;

    load_stage(0, 0); CPA_COMMIT();
    load_stage(1, 1); CPA_COMMIT();

    const u32 aLane  = (u32)((lane & 15) * 56 + ((lane >> 4) << 3)) * 2;
    const u32 wLane4 = (u32)((lane & 15) * 152 + ((lane >> 4) & 1) * 8) * 2;

    for (int kc = 0; kc < 32; kc++) {
        int s = kc & 1;
        CPA_WAIT1();
        __syncthreads();

        u32 sb = dynu + s * GS_STAGE;
        u32 ah[2][2][4], al[2][2][4];
        #pragma unroll
        for (int mt = 0; mt < 2; mt++)
            #pragma unroll
            for (int kk = 0; kk < 2; kk++) {
                u32 off = (u32)((wm * 32 + mt * 16) * 56 + kk * 16) * 2 + aLane;
                ldsm_x4(ah[mt][kk], sb + GS_AH + off);
                ldsm_x4(al[mt][kk], sb + GS_AL + off);
            }
        #pragma unroll
        for (int kk = 0; kk < 2; kk++)
            #pragma unroll
            for (int nn = 0; nn < 8; nn += 2) {
                u32 off = (u32)(kk * 16 * 152 + wn * 64 + nn * 8) * 2 + wLane4;
                u32 bh4[4], bl4[4];
                ldsm_x4t(bh4, sb + GS_WH + off);
                ldsm_x4t(bl4, sb + GS_WL + off);
                #pragma unroll
                for (int mt = 0; mt < 2; mt++) {
                    mma_bf16(acc[mt][nn],     ah[mt][kk], bh4[0], bh4[1]);
                    mma_bf16(acc[mt][nn],     ah[mt][kk], bl4[0], bl4[1]);
                    mma_bf16(acc[mt][nn],     al[mt][kk], bh4[0], bh4[1]);
                    mma_bf16(acc[mt][nn + 1], ah[mt][kk], bh4[2], bh4[3]);
                    mma_bf16(acc[mt][nn + 1], ah[mt][kk], bl4[2], bl4[3]);
                    mma_bf16(acc[mt][nn + 1], al[mt][kk], bh4[2], bh4[3]);
                }
            }

        __syncthreads();
        if (kc + 2 < 32) load_stage(s, kc + 2);
        CPA_COMMIT();
    }

    // ---- epilogue ----
    const int g = lane >> 2, tig = lane & 3;
    if (EPI == 0) {
        #pragma unroll
        for (int mt = 0; mt < 2; mt++) {
            int row = m0 + wm * 32 + mt * 16 + g;
            #pragma unroll
            for (int nn = 0; nn < 8; nn++) {
                int n = n0 + nn * 8 + wn * 64 + 2 * tig;
                *(float2*)(outF + (size_t)row * C_ + n) =
                    make_float2(acc[mt][nn][0], acc[mt][nn][1]);
                *(float2*)(outF + (size_t)(row + 8) * C_ + n) =
                    make_float2(acc[mt][nn][2], acc[mt][nn][3]);
            }
        }
    } else {
        const int hh = (n0 + wn * 64) >> 6;
        #pragma unroll
        for (int mt = 0; mt < 2; mt++) {
            #pragma unroll
            for (int rr = 0; rr < 2; rr++) {
                int row = m0 + wm * 32 + mt * 16 + g + rr * 8;
                int b = row >> 11, l = row & 2047;
                size_t base = ((size_t)(b * H_ + hh) * NQ + l) * 64;
                int ci = rr * 2;
                if (EPI == 1) {
                    #pragma unroll
                    for (int nn = 0; nn < 4; nn++) {
                        int d0 = nn * 8 + 2 * tig;
                        float x1a = acc[mt][nn][ci],     x1b = acc[mt][nn][ci + 1];
                        float x2a = acc[mt][nn + 4][ci], x2b = acc[mt][nn + 4][ci + 1];
                        float2 c1 = *(const float2*)(g_cosT + l * 64 + d0);
                        float2 s1 = *(const float2*)(g_sinT + l * 64 + d0);
                        float2 c2 = *(const float2*)(g_cosT + l * 64 + d0 + 32);
                        float2 s2 = *(const float2*)(g_sinT + l * 64 + d0 + 32);
                        float y1a = scale * (x1a * c1.x - x2a * s1.x);
                        float y1b = scale * (x1b * c1.y - x2b * s1.y);
                        float y2a = scale * (x2a * c2.x + x1a * s2.x);
                        float y2b = scale * (x2b * c2.y + x1b * s2.y);
                        u32 lo1, lo2;
                        u32 hi1 = split_pack_hi(y1a, y1b, lo1);
                        u32 hi2 = split_pack_hi(y2a, y2b, lo2);
                        *(u32*)(Oh + base + d0)      = hi1;
                        *(u32*)(Ol + base + d0)      = lo1;
                        *(u32*)(Oh + base + d0 + 32) = hi2;
                        *(u32*)(Ol + base + d0 + 32) = lo2;
                    }
                } else {
                    #pragma unroll
                    for (int nn = 0; nn < 8; nn++) {
                        int d0 = nn * 8 + 2 * tig;
                        u32 lo;
                        u32 hi = split_pack_hi(acc[mt][nn][ci], acc[mt][nn][ci + 1], lo);
                        *(u32*)(Oh + base + d0) = hi;
                        *(u32*)(Ol + base + d0) = lo;
                    }
                }
            }
        }
    }
}

// Q scale folds log2(e) so attention can use raw ex2.
#define QSCALE (0.125f * 1.4426950408889634f)

__global__ __launch_bounds__(256)
void gemm3_bf16()
{
    int z = blockIdx.z;
    if (z == 0)
        gemm_tc_body<1>(g_Iqh, g_Iql, g_Wqh, g_Wql, nullptr, g_Qh, g_Ql, QSCALE);
    else if (z == 1)
        gemm_tc_body<1>(g_Ikh, g_Ikl, g_Wkh, g_Wkl, nullptr, g_Kh, g_Kl, 1.0f);
    else
        gemm_tc_body<2>(g_Ivh, g_Ivl, g_Wvh, g_Wvl, nullptr, g_Vh, g_Vl, 1.0f);
}
__global__ __launch_bounds__(256)
void gemm1_bf16(float* __restrict__ out)
{
    gemm_tc_body<0>(g_Xh, g_Xl, g_Wph, g_Wpl, out, nullptr, nullptr, 1.0f);
}

// ============================================================================
// Flash attention (exact R12 config, measured ~262us): 64-row/128-thread CTA,
// K double-buffered cp.async, V single-buffered, 4 CTAs/SM, ex2 softmax.
// ============================================================================
#define ROWP 72
#define ATILE (64*ROWP*2)
#define KSTAGE (2*ATILE)
#define ATT_SMEM (2*KSTAGE + KSTAGE)

__global__ __launch_bounds__(128, 4)
void attn_mma(const int* __restrict__ mask)
{
    extern __shared__ char asm_raw[];
    __shared__ int s_mask[2][64];

    const int tid  = threadIdx.x;
    const int wid  = tid >> 5, lane = tid & 31;
    const int g    = lane >> 2, tig = lane & 3;
    const int bh   = blockIdx.x, b = bh >> 4, h = bh & 15;
    const int q0   = blockIdx.y * 64;
    const int r0   = wid * 16;

    const u32 base0 = smem_u32(asm_raw);
    const u32 vbase = base0 + 2 * KSTAGE;

    const bf* Khg = g_Kh + (size_t)bh * NKV * HD;
    const bf* Klg = g_Kl + (size_t)bh * NKV * HD;
    const bf* Vhg = g_Vh + (size_t)bh * NKV * HD;
    const bf* Vlg = g_Vl + (size_t)bh * NKV * HD;

    auto load_K = [&](int s, int t) {
        u32 sb = base0 + s * KSTAGE;
        const bf* kh = Khg + (size_t)t * 64 * HD;
        const bf* kl = Klg + (size_t)t * 64 * HD;
        #pragma unroll
        for (int i = tid; i < 512; i += 128) {
            int row = i >> 3, c8 = i & 7;
            u32 off = (u32)(row * ROWP + c8 * 8) * 2;
            const int gsrc = row * 64 + c8 * 8;
            cpa16(sb + off,         kh + gsrc);
            cpa16(sb + ATILE + off, kl + gsrc);
        }
    };
    auto load_V = [&](int t) {
        const bf* vh = Vhg + (size_t)t * 64 * HD;
        const bf* vl = Vlg + (size_t)t * 64 * HD;
        #pragma unroll
        for (int i = tid; i < 512; i += 128) {
            int row = i >> 3, c8 = i & 7;
            u32 off = (u32)(row * ROWP + c8 * 8) * 2;
            const int gsrc = row * 64 + c8 * 8;
            cpa16(vbase + off,         vh + gsrc);
            cpa16(vbase + ATILE + off, vl + gsrc);
        }
        if (tid < 64) s_mask[t & 1][tid] = mask[b * NKV + t * 64 + tid];
    };

    load_K(0, 0); CPA_COMMIT();
    {
        const bf* qh = g_Qh + ((size_t)bh * NQ + q0) * HD;
        const bf* ql = g_Ql + ((size_t)bh * NQ + q0) * HD;
        bf* dKh = (bf*)(asm_raw + KSTAGE);
        bf* dKl = (bf*)(asm_raw + KSTAGE + ATILE);
        for (int i = tid; i < 512; i += 128) {
            int row = i >> 3, c8 = i & 7;
            *(float4*)(dKh + row * ROWP + c8 * 8) = *(const float4*)(qh + row * 64 + c8 * 8);
            *(float4*)(dKl + row * ROWP + c8 * 8) = *(const float4*)(ql + row * 64 + c8 * 8);
        }
    }
    __syncthreads();

    u32 qh[4][4], ql[4][4];
    {
        u32 rowoff = (u32)((r0 + (lane & 15)) * ROWP + ((lane >> 4) << 3)) * 2;
        #pragma unroll
        for (int kk = 0; kk < 4; kk++) {
            ldsm_x4(qh[kk], base0 + KSTAGE + rowoff + kk * 32);
            ldsm_x4(ql[kk], base0 + KSTAGE + ATILE + rowoff + kk * 32);
        }
    }

    float oacc[8][4];
    #pragma unroll
    for (int nn = 0; nn < 8; nn++)
        #pragma unroll
        for (int p = 0; p < 4; p++) oacc[nn][p] = 0.f;
    float lacc0 = 0.f, lacc1 = 0.f;

    const u32 kAddr4 = (u32)((lane & 7) * ROWP + ((lane >> 3) & 1) * 8
                             + ((lane >> 4) & 1) * 8 * ROWP) * 2;
    const u32 vAddr4 = (u32)((lane & 15) * ROWP + ((lane >> 4) & 1) * 8) * 2;

    for (int t = 0; t < NKV / 64; t++) {
        const int s = t & 1;
        __syncthreads();
        load_V(t); CPA_COMMIT();
        if (t + 1 < NKV / 64) load_K(s ^ 1, t + 1);
        CPA_COMMIT();
        CPA_WAIT2();
        __syncthreads();

        const u32 sbK = base0 + s * KSTAGE;

        float sacc[8][4];
        #pragma unroll
        for (int nn = 0; nn < 8; nn++)
            #pragma unroll
            for (int p = 0; p < 4; p++) sacc[nn][p] = 0.f;

        #pragma unroll
        for (int kk = 0; kk < 4; kk++) {
            #pragma unroll
            for (int nn = 0; nn < 8; nn += 2) {
                u32 off = kAddr4 + (u32)(nn * 8 * ROWP + kk * 16) * 2;
                u32 bh4[4], bl4[4];
                ldsm_x4(bh4, sbK + off);
                ldsm_x4(bl4, sbK + ATILE + off);
                mma_bf16(sacc[nn],     qh[kk], bh4[0], bh4[1]);
                mma_bf16(sacc[nn],     qh[kk], bl4[0], bl4[1]);
                mma_bf16(sacc[nn],     ql[kk], bh4[0], bh4[1]);
                mma_bf16(sacc[nn + 1], qh[kk], bh4[2], bh4[3]);
                mma_bf16(sacc[nn + 1], qh[kk], bl4[2], bl4[3]);
                mma_bf16(sacc[nn + 1], ql[kk], bh4[2], bh4[3]);
            }
        }

        u32 ph[4][4], pl[4][4];
        #pragma unroll
        for (int nn = 0; nn < 8; nn++) {
            int m0 = s_mask[s][nn*8 + 2*tig], m1 = s_mask[s][nn*8 + 2*tig + 1];
            float p00 = m0 ? ex2(sacc[nn][0]) : 0.f;
            float p01 = m1 ? ex2(sacc[nn][1]) : 0.f;
            float p10 = m0 ? ex2(sacc[nn][2]) : 0.f;
            float p11 = m1 ? ex2(sacc[nn][3]) : 0.f;
            lacc0 += p00 + p01;
            lacc1 += p10 + p11;
            int kk = nn >> 1, hi = nn & 1;
            u32 lo;
            ph[kk][hi ? 2 : 0] = split_pack_hi(p00, p01, lo); pl[kk][hi ? 2 : 0] = lo;
            ph[kk][hi ? 3 : 1] = split_pack_hi(p10, p11, lo); pl[kk][hi ? 3 : 1] = lo;
        }

        CPA_WAIT1();
        __syncthreads();

        #pragma unroll
        for (int kk = 0; kk < 4; kk++) {
            #pragma unroll
            for (int nn = 0; nn < 8; nn += 2) {
                u32 off = vAddr4 + (u32)(kk * 16 * ROWP + nn * 8) * 2;
                u32 bh4[4], bl4[4];
                ldsm_x4t(bh4, vbase + off);
                ldsm_x4t(bl4, vbase + ATILE + off);
                mma_bf16(oacc[nn],     ph[kk], bh4[0], bh4[1]);
                mma_bf16(oacc[nn],     ph[kk], bl4[0], bl4[1]);
                mma_bf16(oacc[nn],     pl[kk], bh4[0], bh4[1]);
                mma_bf16(oacc[nn + 1], ph[kk], bh4[2], bh4[3]);
                mma_bf16(oacc[nn + 1], ph[kk], bl4[2], bl4[3]);
                mma_bf16(oacc[nn + 1], pl[kk], bh4[2], bh4[3]);
            }
        }
    }

    lacc0 += __shfl_xor_sync(0xffffffffu, lacc0, 1);
    lacc0 += __shfl_xor_sync(0xffffffffu, lacc0, 2);
    lacc1 += __shfl_xor_sync(0xffffffffu, lacc1, 1);
    lacc1 += __shfl_xor_sync(0xffffffffu, lacc1, 2);
    float inv0 = 1.f / lacc0, inv1 = 1.f / lacc1;

    int row0 = q0 + r0 + g, row1 = row0 + 8;
    size_t base0x = (size_t)(b * NQ + row0) * C_ + h * 64;
    size_t base1x = (size_t)(b * NQ + row1) * C_ + h * 64;
    #pragma unroll
    for (int nn = 0; nn < 8; nn++) {
        int c = nn * 8 + 2 * tig;
        u32 lo;
        u32 hi = split_pack_hi(oacc[nn][0] * inv0, oacc[nn][1] * inv0, lo);
        *(u32*)(g_Xh + base0x + c) = hi;
        *(u32*)(g_Xl + base0x + c) = lo;
        hi = split_pack_hi(oacc[nn][2] * inv1, oacc[nn][3] * inv1, lo);
        *(u32*)(g_Xh + base1x + c) = hi;
        *(u32*)(g_Xl + base1x + c) = lo;
    }
}

// ============================================================================
extern "C" void kernel_launch(void* const* d_in, const int* in_sizes, int n_in,
                              void* d_out, int out_size)
{
    const float* q    = (const float*)d_in[0];
    const float* k    = (const float*)d_in[1];
    const float* v    = (const float*)d_in[2];
    const int*   mask = (const int*)  d_in[3];
    const float* pos  = (const float*)d_in[4];
    const float* qW   = (const float*)d_in[5];
    const float* kW   = (const float*)d_in[6];
    const float* vW   = (const float*)d_in[7];
    const float* pW   = (const float*)d_in[8];
    float* out = (float*)d_out;

    cudaFuncSetAttribute(gemm3_bf16, cudaFuncAttributeMaxDynamicSharedMemorySize, GS_TOTAL);
    cudaFuncSetAttribute(gemm1_bf16, cudaFuncAttributeMaxDynamicSharedMemorySize, GS_TOTAL);
    cudaFuncSetAttribute(attn_mma,  cudaFuncAttributeMaxDynamicSharedMemorySize, ATT_SMEM);

    // merged conversions (one launch, packed 1-D grid, no idle blocks)
    prep_all<<<PREP_BLOCKS, 256>>>(q, k, v, qW, kW, vW, pW, pos);

    // projections + fused RoPE/split epilogues (tensor core)
    gemm3_bf16<<<dim3(C_/128, M_/128, 3), 256, GS_TOTAL>>>();

    // attention (tensor core), 64 q-rows/CTA, 4 CTAs/SM
    attn_mma<<<dim3(B_ * H_, NQ / 64), 128, ATT_SMEM>>>(mask);

    // output projection (tensor core)
    gemm1_bf16<<<dim3(C_/128, M_/128, 1), 256, GS_TOTAL>>>(out);
}

// round 15
// speedup vs baseline: 1.0817x; 1.0212x over previous
#include <cuda_runtime.h>
#include <cuda_bf16.h>
#include <float.h>
#include <math.h>
#include <stdint.h>

#define B_   2
#define NQ   2048
#define NKV  2048
#define C_   1024
#define H_   16
#define HD   64
#define M_   (B_*NQ)

typedef unsigned long long u64;
typedef unsigned int u32;
typedef __nv_bfloat16 bf;

// ---- mma.sync / ldmatrix helpers ----
__device__ __forceinline__ u32 smem_u32(const void* p) {
    u32 a;
    asm("{ .reg .u64 t; cvta.to.shared.u64 t, %1; cvt.u32.u64 %0, t; }" : "=r"(a) : "l"(p));
    return a;
}
__device__ __forceinline__ void mma_bf16(float* c, const u32* a, u32 b0, u32 b1) {
    asm volatile("mma.sync.aligned.m16n8k16.row.col.f32.bf16.bf16.f32 "
        "{%0,%1,%2,%3}, {%4,%5,%6,%7}, {%8,%9}, {%0,%1,%2,%3};"
        : "+f"(c[0]), "+f"(c[1]), "+f"(c[2]), "+f"(c[3])
        : "r"(a[0]), "r"(a[1]), "r"(a[2]), "r"(a[3]), "r"(b0), "r"(b1));
}
__device__ __forceinline__ void ldsm_x4(u32* r, u32 addr) {
    asm volatile("ldmatrix.sync.aligned.m8n8.x4.shared.b16 {%0,%1,%2,%3}, [%4];"
        : "=r"(r[0]), "=r"(r[1]), "=r"(r[2]), "=r"(r[3]) : "r"(addr));
}
__device__ __forceinline__ void ldsm_x4t(u32* r, u32 addr) {
    asm volatile("ldmatrix.sync.aligned.m8n8.x4.trans.shared.b16 {%0,%1,%2,%3}, [%4];"
        : "=r"(r[0]), "=r"(r[1]), "=r"(r[2]), "=r"(r[3]) : "r"(addr));
}
__device__ __forceinline__ void cpa16(u32 dst, const void* src) {
    asm volatile("cp.async.cg.shared.global [%0], [%1], 16;" :: "r"(dst), "l"(src));
}
#define CPA_COMMIT() asm volatile("cp.async.commit_group;" ::: "memory")
#define CPA_WAIT2()  asm volatile("cp.async.wait_group 2;" ::: "memory")
#define CPA_WAIT1()  asm volatile("cp.async.wait_group 1;" ::: "memory")

__device__ __forceinline__ float ex2(float x) {
    float r; asm("ex2.approx.f32 %0, %1;" : "=f"(r) : "f"(x)); return r;
}
// Packed hi/lo split: hi = {bf16(b),bf16(a)}, lo = {bf16(b-hb),bf16(a-ha)}.
// Bit-identical to scalar __float2bfloat16 path (same rn rounding).
__device__ __forceinline__ u32 split_pack_hi(float a, float b, u32& lo) {
    u32 hi;
    asm("cvt.rn.bf16x2.f32 %0, %1, %2;" : "=r"(hi) : "f"(b), "f"(a));
    float fa = __uint_as_float(hi << 16);
    float fb = __uint_as_float(hi & 0xFFFF0000u);
    float la = a - fa, lb = b - fb;
    asm("cvt.rn.bf16x2.f32 %0, %1, %2;" : "=r"(lo) : "f"(lb), "f"(la));
    return hi;
}

// ---- scratch ----
__device__ bf g_Iqh[M_*C_], g_Iql[M_*C_];
__device__ bf g_Ikh[M_*C_], g_Ikl[M_*C_];
__device__ bf g_Ivh[M_*C_], g_Ivl[M_*C_];
__device__ bf g_Wqh[C_*C_], g_Wql[C_*C_];
__device__ bf g_Wkh[C_*C_], g_Wkl[C_*C_];
__device__ bf g_Wvh[C_*C_], g_Wvl[C_*C_];
__device__ bf g_Wph[C_*C_], g_Wpl[C_*C_];
__device__ bf g_Qh[B_*H_*NQ*HD],  g_Ql[B_*H_*NQ*HD];
__device__ bf g_Kh[B_*H_*NKV*HD], g_Kl[B_*H_*NKV*HD];
__device__ bf g_Vh[B_*H_*NKV*HD], g_Vl[B_*H_*NKV*HD];
__device__ bf g_Xh[M_*C_], g_Xl[M_*C_];
__device__ float g_cosT[NKV*HD], g_sinT[NKV*HD];

// ============================================================================
// Merged prep in ONE launch, 1-D packed grid (no idle blocks).
// ============================================================================
#define PREP_BLOCKS 16896

__device__ __forceinline__ void split_one(const float* v, bf* oh, bf* ol, int i) {
    float4 x = ((const float4*)v)[i];
    u32 l0, l1;
    u32 h0 = split_pack_hi(x.x, x.y, l0);
    u32 h1 = split_pack_hi(x.z, x.w, l1);
    ((u32*)oh)[2*i] = h0; ((u32*)oh)[2*i+1] = h1;
    ((u32*)ol)[2*i] = l0; ((u32*)ol)[2*i+1] = l1;
}
__global__ __launch_bounds__(256)
void prep_all(const float* q, const float* k, const float* v,
              const float* wq, const float* wk, const float* wv, const float* wp,
              const float* pos)
{
    int bx = blockIdx.x;
    int tid = threadIdx.x;
    if (bx < 12288) {
        int z = bx >> 12;
        int i = (bx & 4095) * 256 + tid;
        if (z == 0)      split_one(q, g_Iqh, g_Iql, i);
        else if (z == 1) split_one(k, g_Ikh, g_Ikl, i);
        else             split_one(v, g_Ivh, g_Ivl, i);
    } else if (bx < 16384) {
        int r = bx - 12288;
        int z = r >> 10;
        int i = (r & 1023) * 256 + tid;
        if (z == 0)      split_one(wq, g_Wqh, g_Wql, i);
        else if (z == 1) split_one(wk, g_Wkh, g_Wkl, i);
        else if (z == 2) split_one(wv, g_Wvh, g_Wvl, i);
        else             split_one(wp, g_Wph, g_Wpl, i);
    } else {
        int i = (bx - 16384) * 256 + tid;
        float s, c;
        sincosf(pos[i], &s, &c);
        g_cosT[i] = c; g_sinT[i] = s;
    }
}

// ============================================================================
// Split-bf16 tensor-core GEMM (R12 config). __launch_bounds__(256,2) caps regs
// at 128 so 2 CTAs/SM are guaranteed (R14's packed cvt pushed regs to 130 ->
// 1 CTA/SM -> gemm1 79->92us regression; this clamps it back).
// ============================================================================
#define GS_AH 0
#define GS_AL 14336
#define GS_WH 28672
#define GS_WL 38400
#define GS_STAGE 48128
#define GS_TOTAL (2*GS_STAGE)

template<int EPI>
__device__ __forceinline__
void gemm_tc_body(const bf* __restrict__ Ah, const bf* __restrict__ Al,
                  const bf* __restrict__ Wh, const bf* __restrict__ Wl,
                  float* __restrict__ outF, bf* __restrict__ Oh, bf* __restrict__ Ol,
                  float scale)
{
    extern __shared__ char gsm[];
    const u32 dynu = smem_u32(gsm);
    const int tid = threadIdx.x;
    const int wid = tid >> 5, lane = tid & 31;
    const int wm = wid >> 1, wn = wid & 1;
    const int m0 = blockIdx.y * 128, n0 = blockIdx.x * 128;

    auto load_stage = [&](int s, int kc) {
        u32 sb = dynu + s * GS_STAGE;
        #pragma unroll
        for (int i = tid; i < 512; i += 256) {
            int r = i >> 2, c = i & 3;
            u32 off = (u32)(r * 56 + c * 8) * 2;
            cpa16(sb + GS_AH + off, Ah + (size_t)(m0 + r) * C_ + kc * 32 + c * 8);
            cpa16(sb + GS_AL + off, Al + (size_t)(m0 + r) * C_ + kc * 32 + c * 8);
        }
        #pragma unroll
        for (int i = tid; i < 512; i += 256) {
            int r = i >> 4, c = i & 15;
            u32 off = (u32)(r * 152 + c * 8) * 2;
            cpa16(sb + GS_WH + off, Wh + (size_t)(kc * 32 + r) * C_ + n0 + c * 8);
            cpa16(sb + GS_WL + off, Wl + (size_t)(kc * 32 + r) * C_ + n0 + c * 8);
        }
    };

    float acc[2][8][4];
    #pragma unroll
    for (int mt = 0; mt < 2; mt++)
        #pragma unroll
        for (int nn = 0; nn < 8; nn++)
            #pragma unroll
            for (int p = 0; p < 4; p++) acc[mt][nn][p] = 0.f;

    load_stage(0, 0); CPA_COMMIT();
    load_stage(1, 1); CPA_COMMIT();

    const u32 aLane  = (u32)((lane & 15) * 56 + ((lane >> 4) << 3)) * 2;
    const u32 wLane4 = (u32)((lane & 15) * 152 + ((lane >> 4) & 1) * 8) * 2;

    for (int kc = 0; kc < 32; kc++) {
        int s = kc & 1;
        CPA_WAIT1();
        __syncthreads();

        u32 sb = dynu + s * GS_STAGE;
        u32 ah[2][2][4], al[2][2][4];
        #pragma unroll
        for (int mt = 0; mt < 2; mt++)
            #pragma unroll
            for (int kk = 0; kk < 2; kk++) {
                u32 off = (u32)((wm * 32 + mt * 16) * 56 + kk * 16) * 2 + aLane;
                ldsm_x4(ah[mt][kk], sb + GS_AH + off);
                ldsm_x4(al[mt][kk], sb + GS_AL + off);
            }
        #pragma unroll
        for (int kk = 0; kk < 2; kk++)
            #pragma unroll
            for (int nn = 0; nn < 8; nn += 2) {
                u32 off = (u32)(kk * 16 * 152 + wn * 64 + nn * 8) * 2 + wLane4;
                u32 bh4[4], bl4[4];
                ldsm_x4t(bh4, sb + GS_WH + off);
                ldsm_x4t(bl4, sb + GS_WL + off);
                #pragma unroll
                for (int mt = 0; mt < 2; mt++) {
                    mma_bf16(acc[mt][nn],     ah[mt][kk], bh4[0], bh4[1]);
                    mma_bf16(acc[mt][nn],     ah[mt][kk], bl4[0], bl4[1]);
                    mma_bf16(acc[mt][nn],     al[mt][kk], bh4[0], bh4[1]);
                    mma_bf16(acc[mt][nn + 1], ah[mt][kk], bh4[2], bh4[3]);
                    mma_bf16(acc[mt][nn + 1], ah[mt][kk], bl4[2], bl4[3]);
                    mma_bf16(acc[mt][nn + 1], al[mt][kk], bh4[2], bh4[3]);
                }
            }

        __syncthreads();
        if (kc + 2 < 32) load_stage(s, kc + 2);
        CPA_COMMIT();
    }

    // ---- epilogue ----
    const int g = lane >> 2, tig = lane & 3;
    if (EPI == 0) {
        #pragma unroll
        for (int mt = 0; mt < 2; mt++) {
            int row = m0 + wm * 32 + mt * 16 + g;
            #pragma unroll
            for (int nn = 0; nn < 8; nn++) {
                int n = n0 + nn * 8 + wn * 64 + 2 * tig;
                *(float2*)(outF + (size_t)row * C_ + n) =
                    make_float2(acc[mt][nn][0], acc[mt][nn][1]);
                *(float2*)(outF + (size_t)(row + 8) * C_ + n) =
                    make_float2(acc[mt][nn][2], acc[mt][nn][3]);
            }
        }
    } else {
        const int hh = (n0 + wn * 64) >> 6;
        #pragma unroll
        for (int mt = 0; mt < 2; mt++) {
            #pragma unroll
            for (int rr = 0; rr < 2; rr++) {
                int row = m0 + wm * 32 + mt * 16 + g + rr * 8;
                int b = row >> 11, l = row & 2047;
                size_t base = ((size_t)(b * H_ + hh) * NQ + l) * 64;
                int ci = rr * 2;
                if (EPI == 1) {
                    #pragma unroll
                    for (int nn = 0; nn < 4; nn++) {
                        int d0 = nn * 8 + 2 * tig;
                        float x1a = acc[mt][nn][ci],     x1b = acc[mt][nn][ci + 1];
                        float x2a = acc[mt][nn + 4][ci], x2b = acc[mt][nn + 4][ci + 1];
                        float2 c1 = *(const float2*)(g_cosT + l * 64 + d0);
                        float2 s1 = *(const float2*)(g_sinT + l * 64 + d0);
                        float2 c2 = *(const float2*)(g_cosT + l * 64 + d0 + 32);
                        float2 s2 = *(const float2*)(g_sinT + l * 64 + d0 + 32);
                        float y1a = scale * (x1a * c1.x - x2a * s1.x);
                        float y1b = scale * (x1b * c1.y - x2b * s1.y);
                        float y2a = scale * (x2a * c2.x + x1a * s2.x);
                        float y2b = scale * (x2b * c2.y + x1b * s2.y);
                        u32 lo1, lo2;
                        u32 hi1 = split_pack_hi(y1a, y1b, lo1);
                        u32 hi2 = split_pack_hi(y2a, y2b, lo2);
                        *(u32*)(Oh + base + d0)      = hi1;
                        *(u32*)(Ol + base + d0)      = lo1;
                        *(u32*)(Oh + base + d0 + 32) = hi2;
                        *(u32*)(Ol + base + d0 + 32) = lo2;
                    }
                } else {
                    #pragma unroll
                    for (int nn = 0; nn < 8; nn++) {
                        int d0 = nn * 8 + 2 * tig;
                        u32 lo;
                        u32 hi = split_pack_hi(acc[mt][nn][ci], acc[mt][nn][ci + 1], lo);
                        *(u32*)(Oh + base + d0) = hi;
                        *(u32*)(Ol + base + d0) = lo;
                    }
                }
            }
        }
    }
}

// Q scale folds log2(e) so attention can use raw ex2.
#define QSCALE (0.125f * 1.4426950408889634f)

__global__ __launch_bounds__(256, 2)
void gemm3_bf16()
{
    int z = blockIdx.z;
    if (z == 0)
        gemm_tc_body<1>(g_Iqh, g_Iql, g_Wqh, g_Wql, nullptr, g_Qh, g_Ql, QSCALE);
    else if (z == 1)
        gemm_tc_body<1>(g_Ikh, g_Ikl, g_Wkh, g_Wkl, nullptr, g_Kh, g_Kl, 1.0f);
    else
        gemm_tc_body<2>(g_Ivh, g_Ivl, g_Wvh, g_Wvl, nullptr, g_Vh, g_Vl, 1.0f);
}
__global__ __launch_bounds__(256, 2)
void gemm1_bf16(float* __restrict__ out)
{
    gemm_tc_body<0>(g_Xh, g_Xl, g_Wph, g_Wpl, out, nullptr, nullptr, 1.0f);
}

// ============================================================================
// Flash attention (R12 config): 64-row/128-thread CTA, K double-buffered
// cp.async, V single-buffered, 4 CTAs/SM, ex2 softmax, packed splits.
// ============================================================================
#define ROWP 72
#define ATILE (64*ROWP*2)
#define KSTAGE (2*ATILE)
#define ATT_SMEM (2*KSTAGE + KSTAGE)

__global__ __launch_bounds__(128, 4)
void attn_mma(const int* __restrict__ mask)
{
    extern __shared__ char asm_raw[];
    __shared__ int s_mask[2][64];

    const int tid  = threadIdx.x;
    const int wid  = tid >> 5, lane = tid & 31;
    const int g    = lane >> 2, tig = lane & 3;
    const int bh   = blockIdx.x, b = bh >> 4, h = bh & 15;
    const int q0   = blockIdx.y * 64;
    const int r0   = wid * 16;

    const u32 base0 = smem_u32(asm_raw);
    const u32 vbase = base0 + 2 * KSTAGE;

    const bf* Khg = g_Kh + (size_t)bh * NKV * HD;
    const bf* Klg = g_Kl + (size_t)bh * NKV * HD;
    const bf* Vhg = g_Vh + (size_t)bh * NKV * HD;
    const bf* Vlg = g_Vl + (size_t)bh * NKV * HD;

    auto load_K = [&](int s, int t) {
        u32 sb = base0 + s * KSTAGE;
        const bf* kh = Khg + (size_t)t * 64 * HD;
        const bf* kl = Klg + (size_t)t * 64 * HD;
        #pragma unroll
        for (int i = tid; i < 512; i += 128) {
            int row = i >> 3, c8 = i & 7;
            u32 off = (u32)(row * ROWP + c8 * 8) * 2;
            const int gsrc = row * 64 + c8 * 8;
            cpa16(sb + off,         kh + gsrc);
            cpa16(sb + ATILE + off, kl + gsrc);
        }
    };
    auto load_V = [&](int t) {
        const bf* vh = Vhg + (size_t)t * 64 * HD;
        const bf* vl = Vlg + (size_t)t * 64 * HD;
        #pragma unroll
        for (int i = tid; i < 512; i += 128) {
            int row = i >> 3, c8 = i & 7;
            u32 off = (u32)(row * ROWP + c8 * 8) * 2;
            const int gsrc = row * 64 + c8 * 8;
            cpa16(vbase + off,         vh + gsrc);
            cpa16(vbase + ATILE + off, vl + gsrc);
        }
        if (tid < 64) s_mask[t & 1][tid] = mask[b * NKV + t * 64 + tid];
    };

    load_K(0, 0); CPA_COMMIT();
    {
        const bf* qh = g_Qh + ((size_t)bh * NQ + q0) * HD;
        const bf* ql = g_Ql + ((size_t)bh * NQ + q0) * HD;
        bf* dKh = (bf*)(asm_raw + KSTAGE);
        bf* dKl = (bf*)(asm_raw + KSTAGE + ATILE);
        for (int i = tid; i < 512; i += 128) {
            int row = i >> 3, c8 = i & 7;
            *(float4*)(dKh + row * ROWP + c8 * 8) = *(const float4*)(qh + row * 64 + c8 * 8);
            *(float4*)(dKl + row * ROWP + c8 * 8) = *(const float4*)(ql + row * 64 + c8 * 8);
        }
    }
    __syncthreads();

    u32 qh[4][4], ql[4][4];
    {
        u32 rowoff = (u32)((r0 + (lane & 15)) * ROWP + ((lane >> 4) << 3)) * 2;
        #pragma unroll
        for (int kk = 0; kk < 4; kk++) {
            ldsm_x4(qh[kk], base0 + KSTAGE + rowoff + kk * 32);
            ldsm_x4(ql[kk], base0 + KSTAGE + ATILE + rowoff + kk * 32);
        }
    }

    float oacc[8][4];
    #pragma unroll
    for (int nn = 0; nn < 8; nn++)
        #pragma unroll
        for (int p = 0; p < 4; p++) oacc[nn][p] = 0.f;
    float lacc0 = 0.f, lacc1 = 0.f;

    const u32 kAddr4 = (u32)((lane & 7) * ROWP + ((lane >> 3) & 1) * 8
                             + ((lane >> 4) & 1) * 8 * ROWP) * 2;
    const u32 vAddr4 = (u32)((lane & 15) * ROWP + ((lane >> 4) & 1) * 8) * 2;

    for (int t = 0; t < NKV / 64; t++) {
        const int s = t & 1;
        __syncthreads();
        load_V(t); CPA_COMMIT();
        if (t + 1 < NKV / 64) load_K(s ^ 1, t + 1);
        CPA_COMMIT();
        CPA_WAIT2();
        __syncthreads();

        const u32 sbK = base0 + s * KSTAGE;

        float sacc[8][4];
        #pragma unroll
        for (int nn = 0; nn < 8; nn++)
            #pragma unroll
            for (int p = 0; p < 4; p++) sacc[nn][p] = 0.f;

        #pragma unroll
        for (int kk = 0; kk < 4; kk++) {
            #pragma unroll
            for (int nn = 0; nn < 8; nn += 2) {
                u32 off = kAddr4 + (u32)(nn * 8 * ROWP + kk * 16) * 2;
                u32 bh4[4], bl4[4];
                ldsm_x4(bh4, sbK + off);
                ldsm_x4(bl4, sbK + ATILE + off);
                mma_bf16(sacc[nn],     qh[kk], bh4[0], bh4[1]);
                mma_bf16(sacc[nn],     qh[kk], bl4[0], bl4[1]);
                mma_bf16(sacc[nn],     ql[kk], bh4[0], bh4[1]);
                mma_bf16(sacc[nn + 1], qh[kk], bh4[2], bh4[3]);
                mma_bf16(sacc[nn + 1], qh[kk], bl4[2], bl4[3]);
                mma_bf16(sacc[nn + 1], ql[kk], bh4[2], bh4[3]);
            }
        }

        u32 ph[4][4], pl[4][4];
        #pragma unroll
        for (int nn = 0; nn < 8; nn++) {
            int m0 = s_mask[s][nn*8 + 2*tig], m1 = s_mask[s][nn*8 + 2*tig + 1];
            float p00 = m0 ? ex2(sacc[nn][0]) : 0.f;
            float p01 = m1 ? ex2(sacc[nn][1]) : 0.f;
            float p10 = m0 ? ex2(sacc[nn][2]) : 0.f;
            float p11 = m1 ? ex2(sacc[nn][3]) : 0.f;
            lacc0 += p00 + p01;
            lacc1 += p10 + p11;
            int kk = nn >> 1, hi = nn & 1;
            u32 lo;
            ph[kk][hi ? 2 : 0] = split_pack_hi(p00, p01, lo); pl[kk][hi ? 2 : 0] = lo;
            ph[kk][hi ? 3 : 1] = split_pack_hi(p10, p11, lo); pl[kk][hi ? 3 : 1] = lo;
        }

        CPA_WAIT1();
        __syncthreads();

        #pragma unroll
        for (int kk = 0; kk < 4; kk++) {
            #pragma unroll
            for (int nn = 0; nn < 8; nn += 2) {
                u32 off = vAddr4 + (u32)(kk * 16 * ROWP + nn * 8) * 2;
                u32 bh4[4], bl4[4];
                ldsm_x4t(bh4, vbase + off);
                ldsm_x4t(bl4, vbase + ATILE + off);
                mma_bf16(oacc[nn],     ph[kk], bh4[0], bh4[1]);
                mma_bf16(oacc[nn],     ph[kk], bl4[0], bl4[1]);
                mma_bf16(oacc[nn],     pl[kk], bh4[0], bh4[1]);
                mma_bf16(oacc[nn + 1], ph[kk], bh4[2], bh4[3]);
                mma_bf16(oacc[nn + 1], ph[kk], bl4[2], bl4[3]);
                mma_bf16(oacc[nn + 1], pl[kk], bh4[2], bh4[3]);
            }
        }
    }

    lacc0 += __shfl_xor_sync(0xffffffffu, lacc0, 1);
    lacc0 += __shfl_xor_sync(0xffffffffu, lacc0, 2);
    lacc1 += __shfl_xor_sync(0xffffffffu, lacc1, 1);
    lacc1 += __shfl_xor_sync(0xffffffffu, lacc1, 2);
    float inv0 = 1.f / lacc0, inv1 = 1.f / lacc1;

    int row0 = q0 + r0 + g, row1 = row0 + 8;
    size_t base0x = (size_t)(b * NQ + row0) * C_ + h * 64;
    size_t base1x = (size_t)(b * NQ + row1) * C_ + h * 64;
    #pragma unroll
    for (int nn = 0; nn < 8; nn++) {
        int c = nn * 8 + 2 * tig;
        u32 lo;
        u32 hi = split_pack_hi(oacc[nn][0] * inv0, oacc[nn][1] * inv0, lo);
        *(u32*)(g_Xh + base0x + c) = hi;
        *(u32*)(g_Xl + base0x + c) = lo;
        hi = split_pack_hi(oacc[nn][2] * inv1, oacc[nn][3] * inv1, lo);
        *(u32*)(g_Xh + base1x + c) = hi;
        *(u32*)(g_Xl + base1x + c) = lo;
    }
}

// ============================================================================
extern "C" void kernel_launch(void* const* d_in, const int* in_sizes, int n_in,
                              void* d_out, int out_size)
{
    const float* q    = (const float*)d_in[0];
    const float* k    = (const float*)d_in[1];
    const float* v    = (const float*)d_in[2];
    const int*   mask = (const int*)  d_in[3];
    const float* pos  = (const float*)d_in[4];
    const float* qW   = (const float*)d_in[5];
    const float* kW   = (const float*)d_in[6];
    const float* vW   = (const float*)d_in[7];
    const float* pW   = (const float*)d_in[8];
    float* out = (float*)d_out;

    cudaFuncSetAttribute(gemm3_bf16, cudaFuncAttributeMaxDynamicSharedMemorySize, GS_TOTAL);
    cudaFuncSetAttribute(gemm1_bf16, cudaFuncAttributeMaxDynamicSharedMemorySize, GS_TOTAL);
    cudaFuncSetAttribute(attn_mma,  cudaFuncAttributeMaxDynamicSharedMemorySize, ATT_SMEM);

    // merged conversions (one launch, packed 1-D grid)
    prep_all<<<PREP_BLOCKS, 256>>>(q, k, v, qW, kW, vW, pW, pos);

    // projections + fused RoPE/split epilogues (tensor core, 2 CTAs/SM)
    gemm3_bf16<<<dim3(C_/128, M_/128, 3), 256, GS_TOTAL>>>();

    // attention (tensor core), 64 q-rows/CTA, 4 CTAs/SM
    attn_mma<<<dim3(B_ * H_, NQ / 64), 128, ATT_SMEM>>>(mask);

    // output projection (tensor core, 2 CTAs/SM)
    gemm1_bf16<<<dim3(C_/128, M_/128, 1), 256, GS_TOTAL>>>(out);
}